// round 12
// baseline (speedup 1.0000x reference)
#include <cuda_runtime.h>
#include <math.h>
#include <stdint.h>

#define B_  64
#define S_  512
#define I_  300
#define H_  512
#define T_  25
#define G4_ 2048

// d_out layout (float32): [loss(1)] [logits B*S*T] [tags B*S] [pred_mask B*S]
#define LOGITS_OFF 1
#define TAGS_OFF   (1 + B_*S_*T_)
#define PM_OFF     (TAGS_OFF + B_*S_)

typedef unsigned long long u64;

// ---------------- device scratch (static, no allocations) -------------------
__device__ float g_pre[(size_t)2 * S_ * B_ * G4_];   // [dir][t][b][g]
__device__ float g_hf[(size_t)B_ * S_ * H_];         // forward outputs
__device__ float g_hb[(size_t)B_ * S_ * H_];         // backward outputs (un-reversed)
__device__ float g_hbuf[2][2][B_ * H_];              // [buf][dir][b*H+u]
__device__ int   g_len[B_];
__device__ float g_llh[B_];

// two-level per-direction barrier state (monotonic, replay-safe)
__device__ __align__(128) u64 g_grp[8][16];          // [dir*4+grp][0]
__device__ __align__(128) u64 g_mst[2][16];          // [dir][0]
__device__ __align__(128) u64 g_rel[2][16];          // [dir][0]

// ---------------- packed f32x2 FMA ------------------------------------------
__device__ __forceinline__ void ffma2(u64 &d, u64 a, u64 b) {
    asm("fma.rn.f32x2 %0, %1, %2, %0;" : "+l"(d) : "l"(a), "l"(b));
}
__device__ __forceinline__ float f2sum(u64 v) {
    float lo = __uint_as_float((unsigned)(v & 0xffffffffu));
    float hi = __uint_as_float((unsigned)(v >> 32));
    return lo + hi;
}

// ---------------- two-level barrier: 64 blocks of one direction -------------
__device__ __forceinline__ void lstm_barrier(int dir, int grp) {
    __syncthreads();
    if (threadIdx.x == 0) {
        __threadfence();
        u64 tk = atomicAdd(&g_grp[dir * 4 + grp][0], 1ull);
        u64 round = tk >> 4;
        if ((tk & 15ull) == 15ull) {
            u64 t2 = atomicAdd(&g_mst[dir][0], 1ull);
            if ((t2 & 3ull) == 3ull) {
                u64 rel = (t2 >> 2) + 1ull;
                asm volatile("st.release.gpu.global.u64 [%0], %1;"
                             :: "l"(&g_rel[dir][0]), "l"(rel) : "memory");
            }
        }
        u64 target = round + 1ull;
        u64 v;
        do {
            asm volatile("ld.acquire.gpu.global.u64 %0, [%1];"
                         : "=l"(v) : "l"(&g_rel[dir][0]) : "memory");
        } while (v < target);
    }
    __syncthreads();
}

__device__ __forceinline__ float sigf(float x) { return 1.0f / (1.0f + expf(-x)); }

// ---------------- K0: lengths + pred_mask -----------------------------------
__global__ void k_len(const int* __restrict__ mask, float* __restrict__ out) {
    __shared__ int sred[256];
    int b = blockIdx.x;
    int s = 0;
    for (int t = threadIdx.x; t < S_; t += 256) s += mask[b * S_ + t];
    sred[threadIdx.x] = s;
    __syncthreads();
    for (int o = 128; o > 0; o >>= 1) {
        if (threadIdx.x < o) sred[threadIdx.x] += sred[threadIdx.x + o];
        __syncthreads();
    }
    int L = sred[0];
    if (threadIdx.x == 0) g_len[b] = L;
    for (int t = threadIdx.x; t < S_; t += 256)
        out[PM_OFF + b * S_ + t] = (t < L) ? 1.0f : 0.0f;
}

// ---------------- K1: pre-activations x@W_ih^T + b --------------------------
#define KC1 20
__global__ __launch_bounds__(256) void k_pre(const float* __restrict__ x,
                                             const float* __restrict__ Wf,
                                             const float* __restrict__ bf,
                                             const float* __restrict__ Wb,
                                             const float* __restrict__ bb) {
    __shared__ float As[64 * KC1];   // [b][k]
    __shared__ float Bs[64 * KC1];   // [g][k]
    const int gc  = blockIdx.x;
    const int t   = blockIdx.y;
    const int dir = blockIdx.z;
    const float* W    = dir ? Wb : Wf;
    const float* bias = dir ? bb : bf;
    const int g0  = gc * 64;
    const int tid = threadIdx.x;
    const int gg  = tid & 15;
    const int bb_ = tid >> 4;

    int ib[5], ik[5];
    const float* srcA[5];
    const float* srcB[5];
#pragma unroll
    for (int it = 0; it < 5; ++it) {
        int e = tid + 256 * it;
        ib[it] = e / KC1;
        ik[it] = e - ib[it] * KC1;
        int b = ib[it];
        int L = g_len[b];
        int tt = t;
        if (dir && t < L) tt = L - 1 - t;
        srcA[it] = &x[((size_t)b * S_ + tt) * I_ + ik[it]];
        srcB[it] = &W[(size_t)(g0 + b) * I_ + ik[it]];
    }

    float rA[5], rB[5];
#pragma unroll
    for (int it = 0; it < 5; ++it) { rA[it] = srcA[it][0]; rB[it] = srcB[it][0]; }

    u64 acc[4][4];
#pragma unroll
    for (int i = 0; i < 4; ++i)
#pragma unroll
        for (int j = 0; j < 4; ++j) acc[i][j] = 0ull;

    for (int c = 0; c < 15; ++c) {
#pragma unroll
        for (int it = 0; it < 5; ++it) {
            As[ib[it] * KC1 + ik[it]] = rA[it];
            Bs[ib[it] * KC1 + ik[it]] = rB[it];
        }
        __syncthreads();
        if (c < 14) {
            const int k0 = (c + 1) * KC1;
#pragma unroll
            for (int it = 0; it < 5; ++it) { rA[it] = srcA[it][k0]; rB[it] = srcB[it][k0]; }
        }
#pragma unroll
        for (int kq = 0; kq < KC1 / 4; ++kq) {
            ulonglong2 av[4], bv[4];
#pragma unroll
            for (int jj = 0; jj < 4; ++jj)
                av[jj] = *reinterpret_cast<const ulonglong2*>(&As[(bb_ + 16 * jj) * KC1 + kq * 4]);
#pragma unroll
            for (int i = 0; i < 4; ++i)
                bv[i] = *reinterpret_cast<const ulonglong2*>(&Bs[(gg + 16 * i) * KC1 + kq * 4]);
#pragma unroll
            for (int i = 0; i < 4; ++i)
#pragma unroll
                for (int jj = 0; jj < 4; ++jj) {
                    ffma2(acc[i][jj], av[jj].x, bv[i].x);
                    ffma2(acc[i][jj], av[jj].y, bv[i].y);
                }
        }
        __syncthreads();
    }
#pragma unroll
    for (int i = 0; i < 4; ++i) {
        int g = g0 + gg + 16 * i;
        float bv = bias[g];
#pragma unroll
        for (int jj = 0; jj < 4; ++jj) {
            int b = bb_ + 16 * jj;
            g_pre[(((size_t)dir * S_ + t) * B_ + b) * G4_ + g] = f2sum(acc[i][jj]) + bv;
        }
    }
}

// ---------------- K2: persistent bidirectional LSTM scan --------------------
// 128 blocks x 512 threads (4 warps/SMSP). Block j: dir=j>>6, u0=(j&63)*8.
// Thread: kh=tid>>8 (K-half); r=tid&255: rg=r&7 (unit), bgrp=(r>>3)&15, bh=r>>7.
// Each thread: 4 gates x 2 batches (b = bh*32 + bgrp + 16*jj) over its K-half.
// SMEM: Ws[32][516] persistent W_hh; hall[64][516] staged h; red[256][12] partials.
#define WS_STR 516
#define HA_STR 516
#define RED_STR 12
__global__ __launch_bounds__(512, 1) void k_lstm(const float* __restrict__ Whf,
                                                 const float* __restrict__ Whb) {
    extern __shared__ float sm[];
    float* Ws   = sm;                               // 32*516
    float* hall = sm + 32 * WS_STR;                 // 64*516
    float* red  = sm + 32 * WS_STR + 64 * HA_STR;   // 256*12

    const int j    = blockIdx.x;
    const int dir  = j >> 6;
    const int grp  = (j & 63) >> 4;     // barrier group 0..3
    const int u0   = (j & 63) * 8;
    const int tid  = threadIdx.x;
    const int kh   = tid >> 8;          // K-split half
    const int r    = tid & 255;
    const int rg   = r & 7;             // hidden-unit within slice
    const int bgrp = (r >> 3) & 15;
    const int bh   = r >> 7;            // batch half
    const int u    = u0 + rg;
    const int kbeg = kh << 8;           // 0 or 256
    const int bbase = bh * 32 + bgrp;   // batches bbase, bbase+16

    const float* Wh = dir ? Whb : Whf;
    const unsigned hall_s = (unsigned)__cvta_generic_to_shared(hall);

    // load persistent W slice: row rr -> W_hh[(rr>>3)*512 + u0 + (rr&7)][k]
    for (int e = tid; e < 32 * 512; e += 512) {
        int rr = e >> 9, k = e & 511;
        int grow = (rr >> 3) * H_ + u0 + (rr & 7);
        Ws[rr * WS_STR + k] = Wh[(size_t)grow * H_ + k];
    }
    // zero read-buffer (buf 1) for our slice
    for (int e = tid; e < 64 * 8; e += 512) {
        int b = e >> 3, uu = e & 7;
        g_hbuf[1][dir][b * H_ + u0 + uu] = 0.0f;
    }

    float creg[2] = {0.f, 0.f};
    float hreg[2] = {0.f, 0.f};
    int Lb[2] = { g_len[bbase], g_len[bbase + 16] };

    lstm_barrier(dir, grp);

    for (int t = 0; t < S_; ++t) {
        const float* hsrc = g_hbuf[(t & 1) ^ 1][dir];

        // prefetch pre-activation gates early (DRAM latency hides under k-loop)
        float pf[4][2];
        if (kh == 0) {
            const float* pbase = &g_pre[(((size_t)dir * S_ + t) * B_) * G4_];
#pragma unroll
            for (int jj = 0; jj < 2; ++jj) {
                const float* p = pbase + (size_t)(bbase + 16 * jj) * G4_ + u;
                pf[0][jj] = p[0];
                pf[1][jj] = p[512];
                pf[2][jj] = p[1024];
                pf[3][jj] = p[1536];
            }
        }

        // stage full h tile (64x512 floats = 8192 float4s) via cp.async
#pragma unroll
        for (int it = 0; it < 16; ++it) {
            int e = tid + 512 * it;            // 0..8191
            int b = e >> 7, q = e & 127;       // b 0..63, col quad 0..127
            unsigned dst = hall_s + (unsigned)((b * HA_STR + q * 4) * 4);
            const float* src = hsrc + b * 512 + q * 4;
            asm volatile("cp.async.cg.shared.global [%0], [%1], 16;" :: "r"(dst), "l"(src));
        }
        asm volatile("cp.async.commit_group;");
        asm volatile("cp.async.wait_group 0;");
        __syncthreads();

        u64 acc[4][2];
#pragma unroll
        for (int i = 0; i < 4; ++i) { acc[i][0] = 0ull; acc[i][1] = 0ull; }

        const float* wsb[4];
        const float* hbb[2];
#pragma unroll
        for (int i = 0; i < 4; ++i) wsb[i] = &Ws[(rg + 8 * i) * WS_STR + kbeg];
#pragma unroll
        for (int jj = 0; jj < 2; ++jj) hbb[jj] = &hall[(bbase + 16 * jj) * HA_STR + kbeg];

#pragma unroll 8
        for (int kk = 0; kk < 256; kk += 4) {
            ulonglong2 wv[4], hv[2];
#pragma unroll
            for (int i = 0; i < 4; ++i)
                wv[i] = *reinterpret_cast<const ulonglong2*>(wsb[i] + kk);
#pragma unroll
            for (int jj = 0; jj < 2; ++jj)
                hv[jj] = *reinterpret_cast<const ulonglong2*>(hbb[jj] + kk);
#pragma unroll
            for (int i = 0; i < 4; ++i)
#pragma unroll
                for (int jj = 0; jj < 2; ++jj) {
                    ffma2(acc[i][jj], wv[i].x, hv[jj].x);
                    ffma2(acc[i][jj], wv[i].y, hv[jj].y);
                }
        }

        // K-split reduce: half 1 publishes, half 0 combines + gates
        if (kh == 1) {
#pragma unroll
            for (int i = 0; i < 4; ++i)
#pragma unroll
                for (int jj = 0; jj < 2; ++jj)
                    red[r * RED_STR + i * 2 + jj] = f2sum(acc[i][jj]);
        }
        __syncthreads();

        if (kh == 0) {
            float* hdst = g_hbuf[t & 1][dir];
#pragma unroll
            for (int jj = 0; jj < 2; ++jj) {
                int b = bbase + 16 * jj;
                float ig = f2sum(acc[0][jj]) + red[r * RED_STR + 0 * 2 + jj] + pf[0][jj];
                float fg = f2sum(acc[1][jj]) + red[r * RED_STR + 1 * 2 + jj] + pf[1][jj];
                float gg = f2sum(acc[2][jj]) + red[r * RED_STR + 2 * 2 + jj] + pf[2][jj];
                float og = f2sum(acc[3][jj]) + red[r * RED_STR + 3 * 2 + jj] + pf[3][jj];
                int L = Lb[jj];
                bool m = (t < L);
                float cn = sigf(fg) * creg[jj] + sigf(ig) * tanhf(gg);
                float hn = sigf(og) * tanhf(cn);
                if (m) { creg[jj] = cn; hreg[jj] = hn; }
                hdst[b * H_ + u] = hreg[jj];
                float outv = m ? hn : 0.0f;
                if (dir == 0) {
                    g_hf[((size_t)b * S_ + t) * H_ + u] = outv;
                } else {
                    int td = m ? (L - 1 - t) : t;
                    g_hb[((size_t)b * S_ + td) * H_ + u] = outv;
                }
            }
        }
        lstm_barrier(dir, grp);
    }
}

// ---------------- K3: classifier logits = [hf,hb] @ Wc^T + bc ---------------
__global__ __launch_bounds__(256) void k_cls(const float* __restrict__ Wc,
                                             const float* __restrict__ bc,
                                             float* __restrict__ out) {
    __shared__ float hs[128 * 68];
    __shared__ float wcs[32 * 68];
    const int m0  = blockIdx.x * 128;    // flattened row = b*S + t
    const int tid = threadIdx.x;
    const int tq  = tid & 7;
    const int rq  = tid >> 3;
    const int tok0 = tq * 4, r0 = rq * 4;

    u64 acc[4][4];
#pragma unroll
    for (int i = 0; i < 4; ++i)
#pragma unroll
        for (int jm = 0; jm < 4; ++jm) acc[i][jm] = 0ull;

    for (int c = 0; c < 16; ++c) {
        __syncthreads();
        const float* src = (c < 8) ? g_hf : g_hb;
        const int kbase = (c & 7) * 64;
#pragma unroll
        for (int e = tid; e < 2048; e += 256) {
            int r = e >> 4, kq = e & 15;
            *reinterpret_cast<float4*>(&hs[r * 68 + kq * 4]) =
                *reinterpret_cast<const float4*>(&src[(size_t)(m0 + r) * 512 + kbase + kq * 4]);
        }
#pragma unroll
        for (int e = tid; e < 512; e += 256) {
            int tok = e >> 4, kq = e & 15;
            float4 v = make_float4(0.f, 0.f, 0.f, 0.f);
            if (tok < T_)
                v = *reinterpret_cast<const float4*>(&Wc[(size_t)tok * 1024 + c * 64 + kq * 4]);
            *reinterpret_cast<float4*>(&wcs[tok * 68 + kq * 4]) = v;
        }
        __syncthreads();
#pragma unroll
        for (int kk = 0; kk < 64; kk += 4) {
            ulonglong2 av[4], bv[4];
#pragma unroll
            for (int i = 0; i < 4; ++i)
                av[i] = *reinterpret_cast<const ulonglong2*>(&hs[(r0 + i) * 68 + kk]);
#pragma unroll
            for (int jm = 0; jm < 4; ++jm)
                bv[jm] = *reinterpret_cast<const ulonglong2*>(&wcs[(tok0 + jm) * 68 + kk]);
#pragma unroll
            for (int i = 0; i < 4; ++i)
#pragma unroll
                for (int jm = 0; jm < 4; ++jm) {
                    ffma2(acc[i][jm], av[i].x, bv[jm].x);
                    ffma2(acc[i][jm], av[i].y, bv[jm].y);
                }
        }
    }
#pragma unroll
    for (int jm = 0; jm < 4; ++jm) {
        int tok = tok0 + jm;
        if (tok < T_) {
            float bcv = bc[tok];
#pragma unroll
            for (int i = 0; i < 4; ++i)
                out[LOGITS_OFF + (size_t)(m0 + r0 + i) * T_ + tok] = f2sum(acc[i][jm]) + bcv;
        }
    }
}

// ---------------- K4: CRF forward (logsumexp), Viterbi, numerator -----------
__global__ __launch_bounds__(32) void k_crf(const float* __restrict__ out_logits,
                                            const int* __restrict__ labels,
                                            const float* __restrict__ trans,
                                            const float* __restrict__ start,
                                            const float* __restrict__ end,
                                            float* __restrict__ out) {
    __shared__ float trans_s[T_ * T_ + 8];
    __shared__ float sc[32], vv[32];
    __shared__ float end_s[T_], start_s[T_];
    __shared__ unsigned char hist[(S_ - 1) * T_];

    const int b = blockIdx.x;
    const int j = threadIdx.x;
    const int jc = (j < T_) ? j : (T_ - 1);
    const int L = g_len[b];
    const float* em = out_logits + LOGITS_OFF + (size_t)b * S_ * T_;
    const int* lab = labels + b * S_;

    for (int e = j; e < T_ * T_; e += 32) trans_s[e] = trans[e];
    if (j < T_) { end_s[j] = end[j]; start_s[j] = start[j]; }
    __syncwarp();

    float score  = (j < T_) ? (start_s[j] + em[j]) : -1e30f;
    float vscore = score;

    for (int t = 1; t < S_; ++t) {
        sc[j] = score; vv[j] = vscore;
        __syncwarp();
        bool m = (t < L);
        float e = (j < T_) ? em[t * T_ + j] : 0.0f;

        float mx = -1e30f;
        float bmax = -1e30f; int bi = 0;
#pragma unroll 5
        for (int i = 0; i < T_; ++i) {
            float tr = trans_s[i * T_ + jc];
            float v1 = sc[i] + tr;
            mx = fmaxf(mx, v1);
            float v2 = vv[i] + tr;
            if (v2 > bmax) { bmax = v2; bi = i; }
        }
        float smv = 0.0f;
#pragma unroll 5
        for (int i = 0; i < T_; ++i) {
            float v1 = sc[i] + trans_s[i * T_ + jc];
            smv += expf(v1 - mx);
        }
        if (j < T_) {
            hist[(t - 1) * T_ + j] = (unsigned char)(m ? bi : j);
            if (m) {
                score  = mx + logf(smv) + e;
                vscore = bmax + e;
            }
        }
        __syncwarp();
    }
    sc[j] = score; vv[j] = vscore;
    __syncwarp();

    float num = 0.0f;
    for (int t = 1 + j; t < S_; t += 32) {
        if (t < L) {
            int at  = lab[t];
            int at1 = lab[t - 1];
            num += trans_s[at1 * T_ + at] + em[t * T_ + at];
        }
    }
#pragma unroll
    for (int o = 16; o; o >>= 1) num += __shfl_xor_sync(0xffffffffu, num, o);

    if (j == 0) {
        int a0 = lab[0];
        num += start_s[a0] + em[a0] + end_s[lab[L - 1]];
        float mx = -1e30f;
        for (int i = 0; i < T_; ++i) mx = fmaxf(mx, sc[i] + end_s[i]);
        float smv = 0.0f;
        for (int i = 0; i < T_; ++i) smv += expf(sc[i] + end_s[i] - mx);
        float denom = mx + logf(smv);
        g_llh[b] = num - denom;

        float best = -1e30f; int tag = 0;
        for (int i = 0; i < T_; ++i) {
            float v = vv[i] + end_s[i];
            if (v > best) { best = v; tag = i; }
        }
        out[TAGS_OFF + b * S_ + (S_ - 1)] = (float)tag;
        for (int t = S_ - 2; t >= 0; --t) {
            if ((t + 1) < L) tag = hist[t * T_ + tag];
            out[TAGS_OFF + b * S_ + t] = (float)tag;
        }
    }
}

// ---------------- K5: loss reduction ----------------------------------------
__global__ void k_loss(float* __restrict__ out) {
    __shared__ float sv[64];
    __shared__ int scn[64];
    int tid = threadIdx.x;
    sv[tid]  = g_llh[tid];
    scn[tid] = g_len[tid];
    __syncthreads();
    if (tid == 0) {
        float s = 0.0f; int n = 0;
        for (int i = 0; i < 64; ++i) { s += sv[i]; n += scn[i]; }
        out[0] = -(s / (float)n);
    }
}

// ---------------- launch -----------------------------------------------------
extern "C" void kernel_launch(void* const* d_in, const int* in_sizes, int n_in,
                              void* d_out, int out_size) {
    const float* x       = (const float*)d_in[0];
    const float* W_ih_f  = (const float*)d_in[1];
    const float* W_hh_f  = (const float*)d_in[2];
    const float* b_f     = (const float*)d_in[3];
    const float* W_ih_b  = (const float*)d_in[4];
    const float* W_hh_b  = (const float*)d_in[5];
    const float* b_b     = (const float*)d_in[6];
    const float* Wc      = (const float*)d_in[7];
    const float* bc      = (const float*)d_in[8];
    const float* c_start = (const float*)d_in[9];
    const float* c_end   = (const float*)d_in[10];
    const float* c_trans = (const float*)d_in[11];
    const int*   amask   = (const int*)d_in[12];
    const int*   labels  = (const int*)d_in[13];
    float* out = (float*)d_out;

    const size_t smem_lstm = (32 * WS_STR + 64 * HA_STR + 256 * RED_STR) * sizeof(float); // ~206 KB
    cudaFuncSetAttribute(k_lstm, cudaFuncAttributeMaxDynamicSharedMemorySize, (int)smem_lstm);

    k_len<<<B_, 256>>>(amask, out);
    k_pre<<<dim3(32, S_, 2), 256>>>(x, W_ih_f, b_f, W_ih_b, b_b);
    k_lstm<<<128, 512, smem_lstm>>>(W_hh_f, W_hh_b);
    k_cls<<<256, 256>>>(Wc, bc, out);
    k_crf<<<B_, 32>>>(out, labels, c_trans, c_start, c_end, out);
    k_loss<<<1, 64>>>(out);
}

// round 13
// speedup vs baseline: 1.1895x; 1.1895x over previous
#include <cuda_runtime.h>
#include <math.h>
#include <stdint.h>

#define B_  64
#define S_  512
#define I_  300
#define H_  512
#define T_  25
#define G4_ 2048

// d_out layout (float32): [loss(1)] [logits B*S*T] [tags B*S] [pred_mask B*S]
#define LOGITS_OFF 1
#define TAGS_OFF   (1 + B_*S_*T_)
#define PM_OFF     (TAGS_OFF + B_*S_)

typedef unsigned long long u64;

// ---------------- device scratch (static, no allocations) -------------------
__device__ float g_pre[(size_t)2 * S_ * B_ * G4_];   // [dir][t][b][g]
__device__ float g_hf[(size_t)B_ * S_ * H_];         // forward outputs
__device__ float g_hb[(size_t)B_ * S_ * H_];         // backward outputs (un-reversed)
__device__ float g_hbuf[2][2][B_ * H_];              // [buf][dir][b*H+u]
__device__ int   g_len[B_];
__device__ float g_llh[B_];

// two-level per-direction barrier state (monotonic, replay-safe)
__device__ __align__(128) u64 g_grp[8][16];          // [dir*4+grp][0]
__device__ __align__(128) u64 g_mst[2][16];          // [dir][0]
__device__ __align__(128) u64 g_rel[2][16];          // [dir][0]

// ---------------- packed f32x2 FMA ------------------------------------------
__device__ __forceinline__ void ffma2(u64 &d, u64 a, u64 b) {
    asm("fma.rn.f32x2 %0, %1, %2, %0;" : "+l"(d) : "l"(a), "l"(b));
}
__device__ __forceinline__ float f2sum(u64 v) {
    float lo = __uint_as_float((unsigned)(v & 0xffffffffu));
    float hi = __uint_as_float((unsigned)(v >> 32));
    return lo + hi;
}

// ---------------- two-level barrier: 64 blocks of one direction -------------
__device__ __forceinline__ void lstm_barrier(int dir, int grp) {
    __syncthreads();
    if (threadIdx.x == 0) {
        __threadfence();
        u64 tk = atomicAdd(&g_grp[dir * 4 + grp][0], 1ull);
        u64 round = tk >> 4;
        if ((tk & 15ull) == 15ull) {
            u64 t2 = atomicAdd(&g_mst[dir][0], 1ull);
            if ((t2 & 3ull) == 3ull) {
                u64 rel = (t2 >> 2) + 1ull;
                asm volatile("st.release.gpu.global.u64 [%0], %1;"
                             :: "l"(&g_rel[dir][0]), "l"(rel) : "memory");
            }
        }
        u64 target = round + 1ull;
        u64 v;
        do {
            asm volatile("ld.acquire.gpu.global.u64 %0, [%1];"
                         : "=l"(v) : "l"(&g_rel[dir][0]) : "memory");
        } while (v < target);
    }
    __syncthreads();
}

__device__ __forceinline__ float sigf(float x) { return 1.0f / (1.0f + expf(-x)); }

// ---------------- K0: lengths + pred_mask -----------------------------------
__global__ void k_len(const int* __restrict__ mask, float* __restrict__ out) {
    __shared__ int sred[256];
    int b = blockIdx.x;
    int s = 0;
    for (int t = threadIdx.x; t < S_; t += 256) s += mask[b * S_ + t];
    sred[threadIdx.x] = s;
    __syncthreads();
    for (int o = 128; o > 0; o >>= 1) {
        if (threadIdx.x < o) sred[threadIdx.x] += sred[threadIdx.x + o];
        __syncthreads();
    }
    int L = sred[0];
    if (threadIdx.x == 0) g_len[b] = L;
    for (int t = threadIdx.x; t < S_; t += 256)
        out[PM_OFF + b * S_ + t] = (t < L) ? 1.0f : 0.0f;
}

// ---------------- K1: pre-activations x@W_ih^T + b --------------------------
#define KC1 20
__global__ __launch_bounds__(256) void k_pre(const float* __restrict__ x,
                                             const float* __restrict__ Wf,
                                             const float* __restrict__ bf,
                                             const float* __restrict__ Wb,
                                             const float* __restrict__ bb) {
    __shared__ float As[64 * KC1];   // [b][k]
    __shared__ float Bs[64 * KC1];   // [g][k]
    const int gc  = blockIdx.x;
    const int t   = blockIdx.y;
    const int dir = blockIdx.z;
    const float* W    = dir ? Wb : Wf;
    const float* bias = dir ? bb : bf;
    const int g0  = gc * 64;
    const int tid = threadIdx.x;
    const int gg  = tid & 15;
    const int bb_ = tid >> 4;

    int ib[5], ik[5];
    const float* srcA[5];
    const float* srcB[5];
#pragma unroll
    for (int it = 0; it < 5; ++it) {
        int e = tid + 256 * it;
        ib[it] = e / KC1;
        ik[it] = e - ib[it] * KC1;
        int b = ib[it];
        int L = g_len[b];
        int tt = t;
        if (dir && t < L) tt = L - 1 - t;
        srcA[it] = &x[((size_t)b * S_ + tt) * I_ + ik[it]];
        srcB[it] = &W[(size_t)(g0 + b) * I_ + ik[it]];
    }

    float rA[5], rB[5];
#pragma unroll
    for (int it = 0; it < 5; ++it) { rA[it] = srcA[it][0]; rB[it] = srcB[it][0]; }

    u64 acc[4][4];
#pragma unroll
    for (int i = 0; i < 4; ++i)
#pragma unroll
        for (int j = 0; j < 4; ++j) acc[i][j] = 0ull;

    for (int c = 0; c < 15; ++c) {
#pragma unroll
        for (int it = 0; it < 5; ++it) {
            As[ib[it] * KC1 + ik[it]] = rA[it];
            Bs[ib[it] * KC1 + ik[it]] = rB[it];
        }
        __syncthreads();
        if (c < 14) {
            const int k0 = (c + 1) * KC1;
#pragma unroll
            for (int it = 0; it < 5; ++it) { rA[it] = srcA[it][k0]; rB[it] = srcB[it][k0]; }
        }
#pragma unroll
        for (int kq = 0; kq < KC1 / 4; ++kq) {
            ulonglong2 av[4], bv[4];
#pragma unroll
            for (int jj = 0; jj < 4; ++jj)
                av[jj] = *reinterpret_cast<const ulonglong2*>(&As[(bb_ + 16 * jj) * KC1 + kq * 4]);
#pragma unroll
            for (int i = 0; i < 4; ++i)
                bv[i] = *reinterpret_cast<const ulonglong2*>(&Bs[(gg + 16 * i) * KC1 + kq * 4]);
#pragma unroll
            for (int i = 0; i < 4; ++i)
#pragma unroll
                for (int jj = 0; jj < 4; ++jj) {
                    ffma2(acc[i][jj], av[jj].x, bv[i].x);
                    ffma2(acc[i][jj], av[jj].y, bv[i].y);
                }
        }
        __syncthreads();
    }
#pragma unroll
    for (int i = 0; i < 4; ++i) {
        int g = g0 + gg + 16 * i;
        float bv = bias[g];
#pragma unroll
        for (int jj = 0; jj < 4; ++jj) {
            int b = bb_ + 16 * jj;
            g_pre[(((size_t)dir * S_ + t) * B_ + b) * G4_ + g] = f2sum(acc[i][jj]) + bv;
        }
    }
}

// ---------------- K2: persistent bidirectional LSTM scan --------------------
// 128 blocks x 256 threads. Block j: dir=j>>6, u0=(j&63)*8.
// Thread: kh = K-split half (0/1); rg = unit (0..7); bgrp (0..15); 4 gates x 4 batches.
// h tile staged per step via 64x cp.async.bulk (TMA) into padded hall rows.
#define WS_STR 516
#define HA_STR 520
#define RED_STR 20
__global__ __launch_bounds__(256) void k_lstm(const float* __restrict__ Whf,
                                              const float* __restrict__ Whb) {
    extern __shared__ float sm[];
    float* Ws   = sm;                               // 32*516
    float* hall = sm + 32 * WS_STR;                 // 64*520
    float* red  = sm + 32 * WS_STR + 64 * HA_STR;   // 128*20
    __shared__ __align__(8) u64 mbar;

    const int j    = blockIdx.x;
    const int dir  = j >> 6;
    const int grp  = (j & 63) >> 4;     // barrier group 0..3
    const int u0   = (j & 63) * 8;
    const int tid  = threadIdx.x;
    const int kh   = tid >> 7;          // K-split half
    const int r    = tid & 127;
    const int rg   = r & 7;             // hidden-unit within slice
    const int bgrp = r >> 3;            // 0..15 ; b = bgrp + 16*jj
    const int u    = u0 + rg;
    const int kbeg = kh << 8;           // 0 or 256

    const float* Wh = dir ? Whb : Whf;
    const unsigned hall_s = (unsigned)__cvta_generic_to_shared(hall);
    const unsigned mb     = (unsigned)__cvta_generic_to_shared(&mbar);

    if (tid == 0) {
        asm volatile("mbarrier.init.shared.b64 [%0], 1;" :: "r"(mb) : "memory");
    }

    // load persistent W slice: row rr -> W_hh[(rr>>3)*512 + u0 + (rr&7)][k]
    for (int e = tid; e < 32 * 512; e += 256) {
        int rr = e >> 9, k = e & 511;
        int grow = (rr >> 3) * H_ + u0 + (rr & 7);
        Ws[rr * WS_STR + k] = Wh[(size_t)grow * H_ + k];
    }
    // zero read-buffer (buf 1) for our slice
    for (int e = tid; e < 64 * 8; e += 256) {
        int b = e >> 3, uu = e & 7;
        g_hbuf[1][dir][b * H_ + u0 + uu] = 0.0f;
    }

    float creg[4] = {0.f, 0.f, 0.f, 0.f};
    float hreg[4] = {0.f, 0.f, 0.f, 0.f};
    int Lb[4];
#pragma unroll
    for (int jj = 0; jj < 4; ++jj) Lb[jj] = g_len[bgrp + 16 * jj];

    lstm_barrier(dir, grp);

    for (int t = 0; t < S_; ++t) {
        const float* hsrc = g_hbuf[(t & 1) ^ 1][dir];

        // prefetch pre-activation gates early (DRAM latency hides under staging+k-loop)
        float pf[4][4];
        if (kh == 0) {
            const float* pbase = &g_pre[(((size_t)dir * S_ + t) * B_) * G4_];
#pragma unroll
            for (int jj = 0; jj < 4; ++jj) {
                const float* p = pbase + (size_t)(bgrp + 16 * jj) * G4_ + u;
                pf[0][jj] = p[0];
                pf[1][jj] = p[512];
                pf[2][jj] = p[1024];
                pf[3][jj] = p[1536];
            }
        }

        // stage h tile (64 rows x 2KB) via TMA bulk copies into padded rows
        if (tid == 0) {
            asm volatile("mbarrier.arrive.expect_tx.shared.b64 _, [%0], %1;"
                         :: "r"(mb), "r"(64u * 2048u) : "memory");
#pragma unroll 4
            for (int b = 0; b < 64; ++b) {
                unsigned dst = hall_s + (unsigned)(b * HA_STR * 4);
                const float* src = hsrc + b * 512;
                asm volatile(
                    "cp.async.bulk.shared::cta.global.mbarrier::complete_tx::bytes [%0], [%1], %2, [%3];"
                    :: "r"(dst), "l"(src), "r"(2048u), "r"(mb) : "memory");
            }
        }
        {
            const unsigned parity = (unsigned)(t & 1);
            asm volatile(
                "{\n\t"
                ".reg .pred P1;\n\t"
                "WAIT_%=:\n\t"
                "mbarrier.try_wait.parity.acquire.cta.shared::cta.b64 P1, [%0], %1, 0x989680;\n\t"
                "@P1 bra.uni DONE_%=;\n\t"
                "bra.uni WAIT_%=;\n\t"
                "DONE_%=:\n\t"
                "}"
                :: "r"(mb), "r"(parity) : "memory");
        }

        u64 acc[4][4];
#pragma unroll
        for (int i = 0; i < 4; ++i)
#pragma unroll
            for (int jj = 0; jj < 4; ++jj) acc[i][jj] = 0ull;

        const float* wsb[4];
        const float* hbb[4];
#pragma unroll
        for (int i = 0; i < 4; ++i) wsb[i] = &Ws[(rg + 8 * i) * WS_STR + kbeg];
#pragma unroll
        for (int jj = 0; jj < 4; ++jj) hbb[jj] = &hall[(bgrp + 16 * jj) * HA_STR + kbeg];

#pragma unroll 4
        for (int kk = 0; kk < 256; kk += 4) {
            ulonglong2 wv[4], hv[4];
#pragma unroll
            for (int i = 0; i < 4; ++i)
                wv[i] = *reinterpret_cast<const ulonglong2*>(wsb[i] + kk);
#pragma unroll
            for (int jj = 0; jj < 4; ++jj)
                hv[jj] = *reinterpret_cast<const ulonglong2*>(hbb[jj] + kk);
#pragma unroll
            for (int i = 0; i < 4; ++i)
#pragma unroll
                for (int jj = 0; jj < 4; ++jj) {
                    ffma2(acc[i][jj], wv[i].x, hv[jj].x);
                    ffma2(acc[i][jj], wv[i].y, hv[jj].y);
                }
        }

        // K-split reduce: half 1 publishes, half 0 combines + gates
        if (kh == 1) {
#pragma unroll
            for (int i = 0; i < 4; ++i)
#pragma unroll
                for (int jj = 0; jj < 4; ++jj)
                    red[r * RED_STR + i * 4 + jj] = f2sum(acc[i][jj]);
        }
        __syncthreads();

        if (kh == 0) {
            float* hdst = g_hbuf[t & 1][dir];
#pragma unroll
            for (int jj = 0; jj < 4; ++jj) {
                int b = bgrp + 16 * jj;
                float ig = f2sum(acc[0][jj]) + red[r * RED_STR + 0 * 4 + jj] + pf[0][jj];
                float fg = f2sum(acc[1][jj]) + red[r * RED_STR + 1 * 4 + jj] + pf[1][jj];
                float gg = f2sum(acc[2][jj]) + red[r * RED_STR + 2 * 4 + jj] + pf[2][jj];
                float og = f2sum(acc[3][jj]) + red[r * RED_STR + 3 * 4 + jj] + pf[3][jj];
                int L = Lb[jj];
                bool m = (t < L);
                float cn = sigf(fg) * creg[jj] + sigf(ig) * tanhf(gg);
                float hn = sigf(og) * tanhf(cn);
                if (m) { creg[jj] = cn; hreg[jj] = hn; }
                hdst[b * H_ + u] = hreg[jj];
                float outv = m ? hn : 0.0f;
                if (dir == 0) {
                    g_hf[((size_t)b * S_ + t) * H_ + u] = outv;
                } else {
                    int td = m ? (L - 1 - t) : t;
                    g_hb[((size_t)b * S_ + td) * H_ + u] = outv;
                }
            }
        }
        lstm_barrier(dir, grp);
    }
}

// ---------------- K3: classifier logits = [hf,hb] @ Wc^T + bc ---------------
__global__ __launch_bounds__(256) void k_cls(const float* __restrict__ Wc,
                                             const float* __restrict__ bc,
                                             float* __restrict__ out) {
    __shared__ float hs[128 * 68];
    __shared__ float wcs[32 * 68];
    const int m0  = blockIdx.x * 128;    // flattened row = b*S + t
    const int tid = threadIdx.x;
    const int tq  = tid & 7;
    const int rq  = tid >> 3;
    const int tok0 = tq * 4, r0 = rq * 4;

    u64 acc[4][4];
#pragma unroll
    for (int i = 0; i < 4; ++i)
#pragma unroll
        for (int jm = 0; jm < 4; ++jm) acc[i][jm] = 0ull;

    for (int c = 0; c < 16; ++c) {
        __syncthreads();
        const float* src = (c < 8) ? g_hf : g_hb;
        const int kbase = (c & 7) * 64;
#pragma unroll
        for (int e = tid; e < 2048; e += 256) {
            int r = e >> 4, kq = e & 15;
            *reinterpret_cast<float4*>(&hs[r * 68 + kq * 4]) =
                *reinterpret_cast<const float4*>(&src[(size_t)(m0 + r) * 512 + kbase + kq * 4]);
        }
#pragma unroll
        for (int e = tid; e < 512; e += 256) {
            int tok = e >> 4, kq = e & 15;
            float4 v = make_float4(0.f, 0.f, 0.f, 0.f);
            if (tok < T_)
                v = *reinterpret_cast<const float4*>(&Wc[(size_t)tok * 1024 + c * 64 + kq * 4]);
            *reinterpret_cast<float4*>(&wcs[tok * 68 + kq * 4]) = v;
        }
        __syncthreads();
#pragma unroll
        for (int kk = 0; kk < 64; kk += 4) {
            ulonglong2 av[4], bv[4];
#pragma unroll
            for (int i = 0; i < 4; ++i)
                av[i] = *reinterpret_cast<const ulonglong2*>(&hs[(r0 + i) * 68 + kk]);
#pragma unroll
            for (int jm = 0; jm < 4; ++jm)
                bv[jm] = *reinterpret_cast<const ulonglong2*>(&wcs[(tok0 + jm) * 68 + kk]);
#pragma unroll
            for (int i = 0; i < 4; ++i)
#pragma unroll
                for (int jm = 0; jm < 4; ++jm) {
                    ffma2(acc[i][jm], av[i].x, bv[jm].x);
                    ffma2(acc[i][jm], av[i].y, bv[jm].y);
                }
        }
    }
#pragma unroll
    for (int jm = 0; jm < 4; ++jm) {
        int tok = tok0 + jm;
        if (tok < T_) {
            float bcv = bc[tok];
#pragma unroll
            for (int i = 0; i < 4; ++i)
                out[LOGITS_OFF + (size_t)(m0 + r0 + i) * T_ + tok] = f2sum(acc[i][jm]) + bcv;
        }
    }
}

// ---------------- K4: CRF forward (logsumexp), Viterbi, numerator -----------
__global__ __launch_bounds__(32) void k_crf(const float* __restrict__ out_logits,
                                            const int* __restrict__ labels,
                                            const float* __restrict__ trans,
                                            const float* __restrict__ start,
                                            const float* __restrict__ end,
                                            float* __restrict__ out) {
    __shared__ float trans_s[T_ * T_ + 8];
    __shared__ float sc[32], vv[32];
    __shared__ float end_s[T_], start_s[T_];
    __shared__ unsigned char hist[(S_ - 1) * T_];

    const int b = blockIdx.x;
    const int j = threadIdx.x;
    const int jc = (j < T_) ? j : (T_ - 1);
    const int L = g_len[b];
    const float* em = out_logits + LOGITS_OFF + (size_t)b * S_ * T_;
    const int* lab = labels + b * S_;

    for (int e = j; e < T_ * T_; e += 32) trans_s[e] = trans[e];
    if (j < T_) { end_s[j] = end[j]; start_s[j] = start[j]; }
    __syncwarp();

    float score  = (j < T_) ? (start_s[j] + em[j]) : -1e30f;
    float vscore = score;

    for (int t = 1; t < S_; ++t) {
        sc[j] = score; vv[j] = vscore;
        __syncwarp();
        bool m = (t < L);
        float e = (j < T_) ? em[t * T_ + j] : 0.0f;

        float mx = -1e30f;
        float bmax = -1e30f; int bi = 0;
#pragma unroll 5
        for (int i = 0; i < T_; ++i) {
            float tr = trans_s[i * T_ + jc];
            float v1 = sc[i] + tr;
            mx = fmaxf(mx, v1);
            float v2 = vv[i] + tr;
            if (v2 > bmax) { bmax = v2; bi = i; }
        }
        float smv = 0.0f;
#pragma unroll 5
        for (int i = 0; i < T_; ++i) {
            float v1 = sc[i] + trans_s[i * T_ + jc];
            smv += expf(v1 - mx);
        }
        if (j < T_) {
            hist[(t - 1) * T_ + j] = (unsigned char)(m ? bi : j);
            if (m) {
                score  = mx + logf(smv) + e;
                vscore = bmax + e;
            }
        }
        __syncwarp();
    }
    sc[j] = score; vv[j] = vscore;
    __syncwarp();

    float num = 0.0f;
    for (int t = 1 + j; t < S_; t += 32) {
        if (t < L) {
            int at  = lab[t];
            int at1 = lab[t - 1];
            num += trans_s[at1 * T_ + at] + em[t * T_ + at];
        }
    }
#pragma unroll
    for (int o = 16; o; o >>= 1) num += __shfl_xor_sync(0xffffffffu, num, o);

    if (j == 0) {
        int a0 = lab[0];
        num += start_s[a0] + em[a0] + end_s[lab[L - 1]];
        float mx = -1e30f;
        for (int i = 0; i < T_; ++i) mx = fmaxf(mx, sc[i] + end_s[i]);
        float smv = 0.0f;
        for (int i = 0; i < T_; ++i) smv += expf(sc[i] + end_s[i] - mx);
        float denom = mx + logf(smv);
        g_llh[b] = num - denom;

        float best = -1e30f; int tag = 0;
        for (int i = 0; i < T_; ++i) {
            float v = vv[i] + end_s[i];
            if (v > best) { best = v; tag = i; }
        }
        out[TAGS_OFF + b * S_ + (S_ - 1)] = (float)tag;
        for (int t = S_ - 2; t >= 0; --t) {
            if ((t + 1) < L) tag = hist[t * T_ + tag];
            out[TAGS_OFF + b * S_ + t] = (float)tag;
        }
    }
}

// ---------------- K5: loss reduction ----------------------------------------
__global__ void k_loss(float* __restrict__ out) {
    __shared__ float sv[64];
    __shared__ int scn[64];
    int tid = threadIdx.x;
    sv[tid]  = g_llh[tid];
    scn[tid] = g_len[tid];
    __syncthreads();
    if (tid == 0) {
        float s = 0.0f; int n = 0;
        for (int i = 0; i < 64; ++i) { s += sv[i]; n += scn[i]; }
        out[0] = -(s / (float)n);
    }
}

// ---------------- launch -----------------------------------------------------
extern "C" void kernel_launch(void* const* d_in, const int* in_sizes, int n_in,
                              void* d_out, int out_size) {
    const float* x       = (const float*)d_in[0];
    const float* W_ih_f  = (const float*)d_in[1];
    const float* W_hh_f  = (const float*)d_in[2];
    const float* b_f     = (const float*)d_in[3];
    const float* W_ih_b  = (const float*)d_in[4];
    const float* W_hh_b  = (const float*)d_in[5];
    const float* b_b     = (const float*)d_in[6];
    const float* Wc      = (const float*)d_in[7];
    const float* bc      = (const float*)d_in[8];
    const float* c_start = (const float*)d_in[9];
    const float* c_end   = (const float*)d_in[10];
    const float* c_trans = (const float*)d_in[11];
    const int*   amask   = (const int*)d_in[12];
    const int*   labels  = (const int*)d_in[13];
    float* out = (float*)d_out;

    const size_t smem_lstm = (32 * WS_STR + 64 * HA_STR + 128 * RED_STR) * sizeof(float); // ~204.5 KB
    cudaFuncSetAttribute(k_lstm, cudaFuncAttributeMaxDynamicSharedMemorySize, (int)smem_lstm);

    k_len<<<B_, 256>>>(amask, out);
    k_pre<<<dim3(32, S_, 2), 256>>>(x, W_ih_f, b_f, W_ih_b, b_b);
    k_lstm<<<128, 256, smem_lstm>>>(W_hh_f, W_hh_b);
    k_cls<<<256, 256>>>(Wc, bc, out);
    k_crf<<<B_, 32>>>(out, labels, c_trans, c_start, c_end, out);
    k_loss<<<1, 64>>>(out);
}